// round 2
// baseline (speedup 1.0000x reference)
#include <cuda_runtime.h>
#include <math.h>

// Problem constants
#define BB   16
#define NN   2048
#define CIN  64
#define CC   256
#define MTOT (BB*NN)   // 32768

// ---------------- scratch (device globals; no allocation allowed) ----------------
__device__ float g_h[MTOT*CC];          // h after conv2 (residual trunk)
__device__ float g_q[MTOT*CC];          // q (also temp h1, also temp t)
__device__ float g_v[MTOT*CC];          // v
__device__ float g_u[MTOT*CC];          // h - x_r
__device__ float g_attn[(size_t)BB*NN*NN];   // 256 MiB attention matrix
__device__ float g_rscale[BB*NN];       // 1/(eps + colsum)
__device__ float g_bnscale[3*CC];
__device__ float g_bnshift[3*CC];

// ---------------- BN precompute: scale = g*rsqrt(v+eps), shift = b - m*scale ------
__global__ void bn_prep(const float* __restrict__ g1, const float* __restrict__ b1,
                        const float* __restrict__ m1, const float* __restrict__ v1,
                        const float* __restrict__ g2, const float* __restrict__ b2,
                        const float* __restrict__ m2, const float* __restrict__ v2,
                        const float* __restrict__ g3, const float* __restrict__ b3,
                        const float* __restrict__ m3, const float* __restrict__ v3,
                        const float* __restrict__ bt)
{
    int c = threadIdx.x;
    float s;
    s = g1[c] * rsqrtf(v1[c] + 1e-5f);
    g_bnscale[c]       = s; g_bnshift[c]       = b1[c] - m1[c]*s;
    s = g2[c] * rsqrtf(v2[c] + 1e-5f);
    g_bnscale[256 + c] = s; g_bnshift[256 + c] = b2[c] - m2[c]*s;
    s = g3[c] * rsqrtf(v3[c] + 1e-5f);
    // bt folded into bn3 shift: (acc + bt - m)*s + b = acc*s + ((bt-m)*s + b)
    g_bnscale[512 + c] = s; g_bnshift[512 + c] = (bt[c] - m3[c])*s + b3[c];
}

// ---------------- generic tiled GEMM -------------
// C[m,n] = sum_k opA(A)[m,k] * opB(B)[n,k]
//   ATRANS=false: opA(A)[m,k] = A[m*lda + k];  ATRANS=true: A[k*lda + m]
//   BTRANS=false: opB(B)[n,k] = B[n*ldb + k];  BTRANS=true: B[k*ldb + n]
// BM=BN=128, BK=16, 256 threads, 8x8 per thread.
// EPI: 0 plain store; 1 relu(acc*p0[c] + p1[c]); 2 acc + p0[c];
//      4 store p2[h] - acc * p0[z*NN + r]   (x_r epilogue -> u = h - x_r)
// All dims here are multiples of the tile sizes (no guards needed).
template<int EPI, bool ATRANS, bool BTRANS>
__global__ __launch_bounds__(256, 2)
void gemm_k(const float* __restrict__ A, const float* __restrict__ B,
            float* __restrict__ C, int M, int N, int K,
            int lda, int ldb, int ldc,
            long long sA, long long sB, long long sC,
            const float* __restrict__ p0, const float* __restrict__ p1,
            const float* __restrict__ p2)
{
    __shared__ float As[16][132];
    __shared__ float Bs[16][132];

    const int z = blockIdx.z;
    A += (long long)z * sA;
    B += (long long)z * sB;

    const int t  = threadIdx.x;
    const int tx = t & 15;
    const int ty = t >> 4;
    const int m0 = blockIdx.y * 128;
    const int n0 = blockIdx.x * 128;

    float acc[8][8];
#pragma unroll
    for (int i = 0; i < 8; i++)
#pragma unroll
        for (int j = 0; j < 8; j++) acc[i][j] = 0.f;

    for (int k0 = 0; k0 < K; k0 += 16) {
        // ---- load A tile -> As[k][m] ----
#pragma unroll
        for (int i = 0; i < 2; i++) {
            int idx = t + i * 256;   // over 512 float4
            if (!ATRANS) {
                int row = idx >> 2, kq = idx & 3;
                float4 va = *(const float4*)&A[(long long)(m0 + row) * lda + k0 + kq * 4];
                As[kq*4+0][row] = va.x; As[kq*4+1][row] = va.y;
                As[kq*4+2][row] = va.z; As[kq*4+3][row] = va.w;
            } else {
                int kk = idx >> 5, mq = idx & 31;
                float4 va = *(const float4*)&A[(long long)(k0 + kk) * lda + m0 + mq * 4];
                *(float4*)&As[kk][mq * 4] = va;
            }
        }
        // ---- load B tile -> Bs[k][n] ----
#pragma unroll
        for (int i = 0; i < 2; i++) {
            int idx = t + i * 256;
            if (!BTRANS) {
                int row = idx >> 2, kq = idx & 3;
                float4 vb = *(const float4*)&B[(long long)(n0 + row) * ldb + k0 + kq * 4];
                Bs[kq*4+0][row] = vb.x; Bs[kq*4+1][row] = vb.y;
                Bs[kq*4+2][row] = vb.z; Bs[kq*4+3][row] = vb.w;
            } else {
                int kk = idx >> 5, nq = idx & 31;
                float4 vb = *(const float4*)&B[(long long)(k0 + kk) * ldb + n0 + nq * 4];
                *(float4*)&Bs[kk][nq * 4] = vb;
            }
        }
        __syncthreads();

#pragma unroll
        for (int k = 0; k < 16; k++) {
            float4 a0 = *(const float4*)&As[k][ty * 8];
            float4 a1 = *(const float4*)&As[k][ty * 8 + 4];
            float4 b0 = *(const float4*)&Bs[k][tx * 8];
            float4 b1 = *(const float4*)&Bs[k][tx * 8 + 4];
            float av[8] = {a0.x, a0.y, a0.z, a0.w, a1.x, a1.y, a1.z, a1.w};
            float bv[8] = {b0.x, b0.y, b0.z, b0.w, b1.x, b1.y, b1.z, b1.w};
#pragma unroll
            for (int ii = 0; ii < 8; ii++)
#pragma unroll
                for (int jj = 0; jj < 8; jj++)
                    acc[ii][jj] += av[ii] * bv[jj];
        }
        __syncthreads();
    }

    // ---- epilogue ----
    float* Cz = C + (long long)z * sC;
#pragma unroll
    for (int ii = 0; ii < 8; ii++) {
        int r = m0 + ty * 8 + ii;
#pragma unroll
        for (int jh = 0; jh < 2; jh++) {
            int c = n0 + tx * 8 + jh * 4;
            float4 o;
            float a0 = acc[ii][jh*4+0], a1 = acc[ii][jh*4+1];
            float a2 = acc[ii][jh*4+2], a3 = acc[ii][jh*4+3];
            if (EPI == 0) {
                o = make_float4(a0, a1, a2, a3);
            } else if (EPI == 1) {
                o.x = fmaxf(a0 * p0[c+0] + p1[c+0], 0.f);
                o.y = fmaxf(a1 * p0[c+1] + p1[c+1], 0.f);
                o.z = fmaxf(a2 * p0[c+2] + p1[c+2], 0.f);
                o.w = fmaxf(a3 * p0[c+3] + p1[c+3], 0.f);
            } else if (EPI == 2) {
                o = make_float4(a0 + p0[c+0], a1 + p0[c+1], a2 + p0[c+2], a3 + p0[c+3]);
            } else { // EPI == 4 : u = h - x_r ; x_r = acc * rscale[j]
                float rs = p0[z * NN + r];
                const float* hp = p2 + (long long)z * sC + (long long)r * ldc + c;
                o.x = hp[0] - a0 * rs;
                o.y = hp[1] - a1 * rs;
                o.z = hp[2] - a2 * rs;
                o.w = hp[3] - a3 * rs;
            }
            *(float4*)&Cz[(long long)r * ldc + c] = o;
        }
    }
}

// ---------------- softmax over last dim, one block per row (2048 elems) ----------
__global__ void softmax_rows(float* __restrict__ attn)
{
    __shared__ float red[256];
    float* p = attn + (long long)blockIdx.x * NN;
    const int t = threadIdx.x;
    float v[8];
    float mx = -1e30f;
#pragma unroll
    for (int i = 0; i < 8; i++) { v[i] = p[t + i*256]; mx = fmaxf(mx, v[i]); }
    red[t] = mx; __syncthreads();
    for (int s = 128; s > 0; s >>= 1) {
        if (t < s) red[t] = fmaxf(red[t], red[t + s]);
        __syncthreads();
    }
    mx = red[0]; __syncthreads();
    float sum = 0.f;
#pragma unroll
    for (int i = 0; i < 8; i++) { v[i] = __expf(v[i] - mx); sum += v[i]; }
    red[t] = sum; __syncthreads();
    for (int s = 128; s > 0; s >>= 1) {
        if (t < s) red[t] += red[t + s];
        __syncthreads();
    }
    float inv = 1.f / red[0];
#pragma unroll
    for (int i = 0; i < 8; i++) p[t + i*256] = v[i] * inv;
}

// ---------------- column sums of attn -> rscale = 1/(eps + colsum) ---------------
__global__ void colsum_k(const float* __restrict__ attn, float* __restrict__ rscale)
{
    const int b = blockIdx.y;
    const int j = blockIdx.x * 256 + threadIdx.x;
    const float* p = attn + (long long)b * NN * NN + j;
    float s0 = 0.f, s1 = 0.f, s2 = 0.f, s3 = 0.f;
    for (int i = 0; i < NN; i += 4) {
        s0 += p[(long long)(i + 0) * NN];
        s1 += p[(long long)(i + 1) * NN];
        s2 += p[(long long)(i + 2) * NN];
        s3 += p[(long long)(i + 3) * NN];
    }
    rscale[b * NN + j] = 1.f / (1e-9f + (s0 + s1) + (s2 + s3));
}

// ---------------- out[b,c,i] = h[b,i,c] + t[b,i,c]  (transpose via smem) ---------
__global__ void trans_add(const float* __restrict__ h, const float* __restrict__ tt,
                          float* __restrict__ out)
{
    __shared__ float sh[32][33];
    const int b  = blockIdx.z;
    const int i0 = blockIdx.x * 32, c0 = blockIdx.y * 32;
    const int tx = threadIdx.x, ty = threadIdx.y;   // 32 x 8
#pragma unroll
    for (int r = 0; r < 4; r++) {
        int i = i0 + ty + r * 8;
        long long idx = ((long long)b * NN + i) * CC + c0 + tx;
        sh[ty + r * 8][tx] = h[idx] + tt[idx];
    }
    __syncthreads();
#pragma unroll
    for (int r = 0; r < 4; r++) {
        int c = c0 + ty + r * 8;
        out[((long long)b * CC + c) * NN + i0 + tx] = sh[tx][ty + r * 8];
    }
}

// ==================================================================================
extern "C" void kernel_launch(void* const* d_in, const int* in_sizes, int n_in,
                              void* d_out, int out_size)
{
    const float* x   = (const float*)d_in[0];
    const float* w1  = (const float*)d_in[1];
    const float* w2  = (const float*)d_in[2];
    const float* wqk = (const float*)d_in[3];
    const float* wv  = (const float*)d_in[4];
    const float* bv  = (const float*)d_in[5];
    const float* wt  = (const float*)d_in[6];
    const float* bt  = (const float*)d_in[7];
    const float* bn1g = (const float*)d_in[8],  *bn1b = (const float*)d_in[9];
    const float* bn1m = (const float*)d_in[10], *bn1v = (const float*)d_in[11];
    const float* bn2g = (const float*)d_in[12], *bn2b = (const float*)d_in[13];
    const float* bn2m = (const float*)d_in[14], *bn2v = (const float*)d_in[15];
    const float* bn3g = (const float*)d_in[16], *bn3b = (const float*)d_in[17];
    const float* bn3m = (const float*)d_in[18], *bn3v = (const float*)d_in[19];

    float *h, *q, *v, *u, *attn, *rscale, *bns, *bnh;
    cudaGetSymbolAddress((void**)&h, g_h);
    cudaGetSymbolAddress((void**)&q, g_q);
    cudaGetSymbolAddress((void**)&v, g_v);
    cudaGetSymbolAddress((void**)&u, g_u);
    cudaGetSymbolAddress((void**)&attn, g_attn);
    cudaGetSymbolAddress((void**)&rscale, g_rscale);
    cudaGetSymbolAddress((void**)&bns, g_bnscale);
    cudaGetSymbolAddress((void**)&bnh, g_bnshift);

    bn_prep<<<1, 256>>>(bn1g, bn1b, bn1m, bn1v,
                        bn2g, bn2b, bn2m, bn2v,
                        bn3g, bn3b, bn3m, bn3v, bt);

    // h1 = relu(bn1(x @ w1^T))   (into q as temp)
    gemm_k<1, false, false><<<dim3(CC/128, MTOT/128, 1), 256>>>(
        x, w1, q, MTOT, CC, CIN, CIN, CIN, CC, 0, 0, 0, bns, bnh, nullptr);

    // h = relu(bn2(h1 @ w2^T))
    gemm_k<1, false, false><<<dim3(CC/128, MTOT/128, 1), 256>>>(
        q, w2, h, MTOT, CC, CC, CC, CC, CC, 0, 0, 0, bns + 256, bnh + 256, nullptr);

    // q = h @ wqk^T
    gemm_k<0, false, false><<<dim3(CC/128, MTOT/128, 1), 256>>>(
        h, wqk, q, MTOT, CC, CC, CC, CC, CC, 0, 0, 0, nullptr, nullptr, nullptr);

    // v = h @ wv^T + bv
    gemm_k<2, false, false><<<dim3(CC/128, MTOT/128, 1), 256>>>(
        h, wv, v, MTOT, CC, CC, CC, CC, CC, 0, 0, 0, bv, nullptr, nullptr);

    // energy[b,i,j] = q[b,i,:] . q[b,j,:]   (batched)
    gemm_k<0, false, false><<<dim3(NN/128, NN/128, BB), 256>>>(
        q, q, attn, NN, NN, CC, CC, CC, NN,
        (long long)NN*CC, (long long)NN*CC, (long long)NN*NN,
        nullptr, nullptr, nullptr);

    // row softmax
    softmax_rows<<<MTOT, 256>>>(attn);

    // column-sum L1 renorm factors
    colsum_k<<<dim3(NN/256, BB), 256>>>(attn, rscale);

    // u[b,j,c] = h - (sum_i attn[i,j] v[i,c]) * rscale[j]
    // A = attn read as A[k=i, m=j] (ATRANS); B = v read as B[k=i, n=c] (BTRANS)
    gemm_k<4, true, true><<<dim3(CC/128, NN/128, BB), 256>>>(
        attn, v, u, NN, CC, NN, NN, CC, CC,
        (long long)NN*NN, (long long)NN*CC, (long long)NN*CC,
        rscale, nullptr, h);

    // t = relu(bn3(u @ wt^T + bt))   (into q as temp; bt folded into shift)
    gemm_k<1, false, false><<<dim3(CC/128, MTOT/128, 1), 256>>>(
        u, wt, q, MTOT, CC, CC, CC, CC, CC, 0, 0, 0, bns + 512, bnh + 512, nullptr);

    // out[b,c,i] = h + t, transposed
    trans_add<<<dim3(NN/32, CC/32, BB), dim3(32, 8)>>>(h, q, (float*)d_out);
}

// round 3
// speedup vs baseline: 2.2034x; 2.2034x over previous
#include <cuda_runtime.h>
#include <math.h>
#include <stdint.h>

// Problem constants
#define BB   16
#define NN   2048
#define CIN  64
#define CC   256
#define MTOT (BB*NN)   // 32768

// ---------------- scratch (device globals; no allocation allowed) ----------------
__device__ float g_h[MTOT*CC];
__device__ float g_q[MTOT*CC];
__device__ float g_v[MTOT*CC];
__device__ float g_u[MTOT*CC];
__device__ float g_attn[(size_t)BB*NN*NN];   // 256 MiB attention matrix
__device__ float g_rscale[BB*NN];
__device__ float g_bnscale[3*CC];
__device__ float g_bnshift[3*CC];

// ---------------- BN precompute ----------------
__global__ void bn_prep(const float* __restrict__ g1, const float* __restrict__ b1,
                        const float* __restrict__ m1, const float* __restrict__ v1,
                        const float* __restrict__ g2, const float* __restrict__ b2,
                        const float* __restrict__ m2, const float* __restrict__ v2,
                        const float* __restrict__ g3, const float* __restrict__ b3,
                        const float* __restrict__ m3, const float* __restrict__ v3,
                        const float* __restrict__ bt)
{
    int c = threadIdx.x;
    float s;
    s = g1[c] * rsqrtf(v1[c] + 1e-5f);
    g_bnscale[c]       = s; g_bnshift[c]       = b1[c] - m1[c]*s;
    s = g2[c] * rsqrtf(v2[c] + 1e-5f);
    g_bnscale[256 + c] = s; g_bnshift[256 + c] = b2[c] - m2[c]*s;
    s = g3[c] * rsqrtf(v3[c] + 1e-5f);
    g_bnscale[512 + c] = s; g_bnshift[512 + c] = (bt[c] - m3[c])*s + b3[c];
}

__device__ __forceinline__ uint32_t cvt_tf32(float x) {
    uint32_t u;
    asm("cvt.rna.tf32.f32 %0, %1;" : "=r"(u) : "f"(x));
    return u;
}

// ---------------- tensor-core tiled GEMM (tf32 mma.sync) -------------
// C[m,n] = sum_k opA(A)[m,k] * opB(B)[n,k]
//   ATRANS=false: opA(A)[m,k] = A[m*lda + k];  ATRANS=true: A[k*lda + m]
//   BTRANS similarly for B[n,k] vs B[k*ldb + n]
// Tile: BM=BN=128, BK=16; 256 threads = 8 warps, each warp 64x32 via 4x4 m16n8k8.
// smem layouts (tf32-converted bit patterns stored as float):
//   non-trans operand: [row][k]  stride 20  (conflict-free frag reads)
//   trans operand:     [k][row]  stride 136 (conflict-free stores+frag reads)
// EPI: 0 plain; 1 relu(acc*p0[c]+p1[c]); 2 acc+p0[c]; 4 p2[r,c] - acc*p0[z*NN+r]
template<int EPI, bool ATRANS, bool BTRANS>
__global__ __launch_bounds__(256, 2)
void gemm_tc(const float* __restrict__ A, const float* __restrict__ B,
             float* __restrict__ C, int K,
             int lda, int ldb, int ldc,
             long long sA, long long sB, long long sC,
             const float* __restrict__ p0, const float* __restrict__ p1,
             const float* __restrict__ p2)
{
    __shared__ float As[2560];   // max(128*20, 16*136)
    __shared__ float Bs[2560];

    const int z = blockIdx.z;
    A += (long long)z * sA;
    B += (long long)z * sB;

    const int t    = threadIdx.x;
    const int lane = t & 31;
    const int wid  = t >> 5;
    const int wm   = wid >> 2;      // 0..1  (rows of 64)
    const int wn   = wid & 3;       // 0..3  (cols of 32)
    const int grp  = lane >> 2;     // 0..7
    const int qid  = lane & 3;      // 0..3
    const int m0   = blockIdx.y * 128;
    const int n0   = blockIdx.x * 128;

    float acc[4][4][4];
#pragma unroll
    for (int i = 0; i < 4; i++)
#pragma unroll
        for (int j = 0; j < 4; j++)
#pragma unroll
            for (int e = 0; e < 4; e++) acc[i][j][e] = 0.f;

    for (int k0 = 0; k0 < K; k0 += 16) {
        // ---- load A tile ----
        if (!ATRANS) {
#pragma unroll
            for (int i = 0; i < 2; i++) {
                int idx = t + i * 256;           // 512 float4 over [128][16]
                int row = idx >> 2, kq = idx & 3;
                float4 va = *(const float4*)&A[(long long)(m0 + row) * lda + k0 + kq * 4];
                float4 vo;
                vo.x = __uint_as_float(cvt_tf32(va.x));
                vo.y = __uint_as_float(cvt_tf32(va.y));
                vo.z = __uint_as_float(cvt_tf32(va.z));
                vo.w = __uint_as_float(cvt_tf32(va.w));
                *(float4*)&As[row * 20 + kq * 4] = vo;
            }
        } else {
#pragma unroll
            for (int i = 0; i < 2; i++) {
                int idx = t + i * 256;           // 512 float4 over [16][128]
                int kk = idx >> 5, mq = idx & 31;
                float4 va = *(const float4*)&A[(long long)(k0 + kk) * lda + m0 + mq * 4];
                float4 vo;
                vo.x = __uint_as_float(cvt_tf32(va.x));
                vo.y = __uint_as_float(cvt_tf32(va.y));
                vo.z = __uint_as_float(cvt_tf32(va.z));
                vo.w = __uint_as_float(cvt_tf32(va.w));
                *(float4*)&As[kk * 136 + mq * 4] = vo;
            }
        }
        // ---- load B tile ----
        if (!BTRANS) {
#pragma unroll
            for (int i = 0; i < 2; i++) {
                int idx = t + i * 256;
                int row = idx >> 2, kq = idx & 3;
                float4 vb = *(const float4*)&B[(long long)(n0 + row) * ldb + k0 + kq * 4];
                float4 vo;
                vo.x = __uint_as_float(cvt_tf32(vb.x));
                vo.y = __uint_as_float(cvt_tf32(vb.y));
                vo.z = __uint_as_float(cvt_tf32(vb.z));
                vo.w = __uint_as_float(cvt_tf32(vb.w));
                *(float4*)&Bs[row * 20 + kq * 4] = vo;
            }
        } else {
#pragma unroll
            for (int i = 0; i < 2; i++) {
                int idx = t + i * 256;
                int kk = idx >> 5, nq = idx & 31;
                float4 vb = *(const float4*)&B[(long long)(k0 + kk) * ldb + n0 + nq * 4];
                float4 vo;
                vo.x = __uint_as_float(cvt_tf32(vb.x));
                vo.y = __uint_as_float(cvt_tf32(vb.y));
                vo.z = __uint_as_float(cvt_tf32(vb.z));
                vo.w = __uint_as_float(cvt_tf32(vb.w));
                *(float4*)&Bs[kk * 136 + nq * 4] = vo;
            }
        }
        __syncthreads();

        // ---- 2 k8 steps ----
#pragma unroll
        for (int ks = 0; ks < 16; ks += 8) {
            uint32_t a[4][4], b[4][2];
#pragma unroll
            for (int i = 0; i < 4; i++) {
                int rb = wm * 64 + i * 16 + grp;
                if (!ATRANS) {
                    a[i][0] = __float_as_uint(As[(rb    ) * 20 + ks + qid]);
                    a[i][1] = __float_as_uint(As[(rb + 8) * 20 + ks + qid]);
                    a[i][2] = __float_as_uint(As[(rb    ) * 20 + ks + 4 + qid]);
                    a[i][3] = __float_as_uint(As[(rb + 8) * 20 + ks + 4 + qid]);
                } else {
                    a[i][0] = __float_as_uint(As[(ks + qid    ) * 136 + rb]);
                    a[i][1] = __float_as_uint(As[(ks + qid    ) * 136 + rb + 8]);
                    a[i][2] = __float_as_uint(As[(ks + qid + 4) * 136 + rb]);
                    a[i][3] = __float_as_uint(As[(ks + qid + 4) * 136 + rb + 8]);
                }
            }
#pragma unroll
            for (int j = 0; j < 4; j++) {
                int nb = wn * 32 + j * 8 + grp;
                if (!BTRANS) {
                    b[j][0] = __float_as_uint(Bs[nb * 20 + ks + qid]);
                    b[j][1] = __float_as_uint(Bs[nb * 20 + ks + 4 + qid]);
                } else {
                    b[j][0] = __float_as_uint(Bs[(ks + qid    ) * 136 + nb]);
                    b[j][1] = __float_as_uint(Bs[(ks + qid + 4) * 136 + nb]);
                }
            }
#pragma unroll
            for (int i = 0; i < 4; i++)
#pragma unroll
                for (int j = 0; j < 4; j++) {
                    asm volatile(
                        "mma.sync.aligned.m16n8k8.row.col.f32.tf32.tf32.f32 "
                        "{%0,%1,%2,%3}, {%4,%5,%6,%7}, {%8,%9}, {%0,%1,%2,%3};\n"
                        : "+f"(acc[i][j][0]), "+f"(acc[i][j][1]),
                          "+f"(acc[i][j][2]), "+f"(acc[i][j][3])
                        : "r"(a[i][0]), "r"(a[i][1]), "r"(a[i][2]), "r"(a[i][3]),
                          "r"(b[j][0]), "r"(b[j][1]));
                }
        }
        __syncthreads();
    }

    // ---- epilogue ----
    float* Cz = C + (long long)z * sC;
#pragma unroll
    for (int i = 0; i < 4; i++) {
        int r0 = m0 + wm * 64 + i * 16 + grp;
        int r1 = r0 + 8;
#pragma unroll
        for (int j = 0; j < 4; j++) {
            int c = n0 + wn * 32 + j * 8 + qid * 2;
            float d0 = acc[i][j][0], d1 = acc[i][j][1];
            float d2 = acc[i][j][2], d3 = acc[i][j][3];
            float2 o0, o1;
            if (EPI == 0) {
                o0 = make_float2(d0, d1);
                o1 = make_float2(d2, d3);
            } else if (EPI == 1) {
                float s0 = p0[c], s1 = p0[c+1], h0 = p1[c], h1 = p1[c+1];
                o0.x = fmaxf(d0 * s0 + h0, 0.f);
                o0.y = fmaxf(d1 * s1 + h1, 0.f);
                o1.x = fmaxf(d2 * s0 + h0, 0.f);
                o1.y = fmaxf(d3 * s1 + h1, 0.f);
            } else if (EPI == 2) {
                float h0 = p0[c], h1 = p0[c+1];
                o0 = make_float2(d0 + h0, d1 + h1);
                o1 = make_float2(d2 + h0, d3 + h1);
            } else { // EPI == 4 : u = h - acc*rscale[row]
                float rsa = p0[z * NN + r0];
                float rsb = p0[z * NN + r1];
                const float* hpz = p2 + (long long)z * sC;
                o0.x = hpz[(long long)r0 * ldc + c    ] - d0 * rsa;
                o0.y = hpz[(long long)r0 * ldc + c + 1] - d1 * rsa;
                o1.x = hpz[(long long)r1 * ldc + c    ] - d2 * rsb;
                o1.y = hpz[(long long)r1 * ldc + c + 1] - d3 * rsb;
            }
            *(float2*)&Cz[(long long)r0 * ldc + c] = o0;
            *(float2*)&Cz[(long long)r1 * ldc + c] = o1;
        }
    }
}

// ---------------- softmax over last dim, one block per row (2048 elems) ----------
__global__ void softmax_rows(float* __restrict__ attn)
{
    __shared__ float red[256];
    float* p = attn + (long long)blockIdx.x * NN;
    const int t = threadIdx.x;
    float v[8];
    float mx = -1e30f;
#pragma unroll
    for (int i = 0; i < 8; i++) { v[i] = p[t + i*256]; mx = fmaxf(mx, v[i]); }
    red[t] = mx; __syncthreads();
    for (int s = 128; s > 0; s >>= 1) {
        if (t < s) red[t] = fmaxf(red[t], red[t + s]);
        __syncthreads();
    }
    mx = red[0]; __syncthreads();
    float sum = 0.f;
#pragma unroll
    for (int i = 0; i < 8; i++) { v[i] = __expf(v[i] - mx); sum += v[i]; }
    red[t] = sum; __syncthreads();
    for (int s = 128; s > 0; s >>= 1) {
        if (t < s) red[t] += red[t + s];
        __syncthreads();
    }
    float inv = 1.f / red[0];
#pragma unroll
    for (int i = 0; i < 8; i++) p[t + i*256] = v[i] * inv;
}

// ---------------- column sums of attn -> rscale = 1/(eps + colsum) ---------------
__global__ void colsum_k(const float* __restrict__ attn, float* __restrict__ rscale)
{
    const int b = blockIdx.y;
    const int j = blockIdx.x * 256 + threadIdx.x;
    const float* p = attn + (long long)b * NN * NN + j;
    float s0 = 0.f, s1 = 0.f, s2 = 0.f, s3 = 0.f;
    for (int i = 0; i < NN; i += 4) {
        s0 += p[(long long)(i + 0) * NN];
        s1 += p[(long long)(i + 1) * NN];
        s2 += p[(long long)(i + 2) * NN];
        s3 += p[(long long)(i + 3) * NN];
    }
    rscale[b * NN + j] = 1.f / (1e-9f + (s0 + s1) + (s2 + s3));
}

// ---------------- out[b,c,i] = h[b,i,c] + t[b,i,c]  (transpose via smem) ---------
__global__ void trans_add(const float* __restrict__ h, const float* __restrict__ tt,
                          float* __restrict__ out)
{
    __shared__ float sh[32][33];
    const int b  = blockIdx.z;
    const int i0 = blockIdx.x * 32, c0 = blockIdx.y * 32;
    const int tx = threadIdx.x, ty = threadIdx.y;   // 32 x 8
#pragma unroll
    for (int r = 0; r < 4; r++) {
        int i = i0 + ty + r * 8;
        long long idx = ((long long)b * NN + i) * CC + c0 + tx;
        sh[ty + r * 8][tx] = h[idx] + tt[idx];
    }
    __syncthreads();
#pragma unroll
    for (int r = 0; r < 4; r++) {
        int c = c0 + ty + r * 8;
        out[((long long)b * CC + c) * NN + i0 + tx] = sh[tx][ty + r * 8];
    }
}

// ==================================================================================
extern "C" void kernel_launch(void* const* d_in, const int* in_sizes, int n_in,
                              void* d_out, int out_size)
{
    const float* x   = (const float*)d_in[0];
    const float* w1  = (const float*)d_in[1];
    const float* w2  = (const float*)d_in[2];
    const float* wqk = (const float*)d_in[3];
    const float* wv  = (const float*)d_in[4];
    const float* bv  = (const float*)d_in[5];
    const float* wt  = (const float*)d_in[6];
    const float* bt  = (const float*)d_in[7];
    const float* bn1g = (const float*)d_in[8],  *bn1b = (const float*)d_in[9];
    const float* bn1m = (const float*)d_in[10], *bn1v = (const float*)d_in[11];
    const float* bn2g = (const float*)d_in[12], *bn2b = (const float*)d_in[13];
    const float* bn2m = (const float*)d_in[14], *bn2v = (const float*)d_in[15];
    const float* bn3g = (const float*)d_in[16], *bn3b = (const float*)d_in[17];
    const float* bn3m = (const float*)d_in[18], *bn3v = (const float*)d_in[19];

    float *h, *q, *v, *u, *attn, *rscale, *bns, *bnh;
    cudaGetSymbolAddress((void**)&h, g_h);
    cudaGetSymbolAddress((void**)&q, g_q);
    cudaGetSymbolAddress((void**)&v, g_v);
    cudaGetSymbolAddress((void**)&u, g_u);
    cudaGetSymbolAddress((void**)&attn, g_attn);
    cudaGetSymbolAddress((void**)&rscale, g_rscale);
    cudaGetSymbolAddress((void**)&bns, g_bnscale);
    cudaGetSymbolAddress((void**)&bnh, g_bnshift);

    bn_prep<<<1, 256>>>(bn1g, bn1b, bn1m, bn1v,
                        bn2g, bn2b, bn2m, bn2v,
                        bn3g, bn3b, bn3m, bn3v, bt);

    // h1 = relu(bn1(x @ w1^T))   (into q as temp)
    gemm_tc<1, false, false><<<dim3(CC/128, MTOT/128, 1), 256>>>(
        x, w1, q, CIN, CIN, CIN, CC, 0, 0, 0, bns, bnh, nullptr);

    // h = relu(bn2(h1 @ w2^T))
    gemm_tc<1, false, false><<<dim3(CC/128, MTOT/128, 1), 256>>>(
        q, w2, h, CC, CC, CC, CC, 0, 0, 0, bns + 256, bnh + 256, nullptr);

    // q = h @ wqk^T
    gemm_tc<0, false, false><<<dim3(CC/128, MTOT/128, 1), 256>>>(
        h, wqk, q, CC, CC, CC, CC, 0, 0, 0, nullptr, nullptr, nullptr);

    // v = h @ wv^T + bv
    gemm_tc<2, false, false><<<dim3(CC/128, MTOT/128, 1), 256>>>(
        h, wv, v, CC, CC, CC, CC, 0, 0, 0, bv, nullptr, nullptr);

    // energy[b,i,j] = q[b,i,:] . q[b,j,:]   (batched)
    gemm_tc<0, false, false><<<dim3(NN/128, NN/128, BB), 256>>>(
        q, q, attn, CC, CC, CC, NN,
        (long long)NN*CC, (long long)NN*CC, (long long)NN*NN,
        nullptr, nullptr, nullptr);

    // row softmax
    softmax_rows<<<MTOT, 256>>>(attn);

    // column-sum L1 renorm factors
    colsum_k<<<dim3(NN/256, BB), 256>>>(attn, rscale);

    // u[b,j,c] = h - (sum_i attn[i,j] v[i,c]) * rscale[j]
    // A = attn read as A[k=i, m=j] (ATRANS); B = v read as B[k=i, n=c] (BTRANS)
    gemm_tc<4, true, true><<<dim3(CC/128, NN/128, BB), 256>>>(
        attn, v, u, NN, NN, CC, CC,
        (long long)NN*NN, (long long)NN*CC, (long long)NN*CC,
        rscale, nullptr, h);

    // t = relu(bn3(u @ wt^T + bt))   (into q as temp; bt folded into shift)
    gemm_tc<1, false, false><<<dim3(CC/128, MTOT/128, 1), 256>>>(
        u, wt, q, CC, CC, CC, CC, 0, 0, 0, bns + 512, bnh + 512, nullptr);

    // out[b,c,i] = h + t, transposed
    trans_add<<<dim3(NN/32, CC/32, BB), dim3(32, 8)>>>(h, q, (float*)d_out);
}